// round 3
// baseline (speedup 1.0000x reference)
#include <cuda_runtime.h>
#include <cuda_bf16.h>
#include <stdint.h>

// ---------------- problem constants ----------------
#define NMAX 50000
#define EMAX 800000
#define D    128

// ---------------- device scratch (no allocations allowed) ----------------
__device__ int   g_cnt[NMAX + 1];
__device__ int   g_rp[NMAX + 1];     // row_ptr (CSR by dst)
__device__ int   g_fill[NMAX];       // fill cursors
__device__ float g_inv[NMAX];        // 1/max(deg,1)
__device__ int   g_col[EMAX];        // src indices sorted by dst
__device__ float g_h1[NMAX * D];
__device__ float g_h2[NMAX * D];
__device__ float g_agg[NMAX * D];
__device__ int   g_is64;

// ---------------- edge-index dtype detection ----------------
// If the [2,E] index tensor is int64, every odd 32-bit word is the (zero)
// high half of a value < 50000. If it's int32, odd words are random indices.
__global__ void detect_kernel(const void* ei, int E) {
    const int* p = (const int*)ei;
    int t = threadIdx.x;
    int m = min(E, 2048);
    int bad = 0;
    for (int i = t; i < m; i += blockDim.x) bad |= p[2 * i + 1];
    __shared__ int s;
    if (t == 0) s = 0;
    __syncthreads();
    atomicOr(&s, bad);
    __syncthreads();
    if (t == 0) g_is64 = (s == 0) ? 1 : 0;
}

__device__ __forceinline__ int load_idx(const void* ei, long long pos) {
    if (g_is64) return (int)((const long long*)ei)[pos];
    return ((const int*)ei)[pos];
}

// ---------------- CSR build ----------------
__global__ void zero_cnt_kernel(int n) {
    int i = blockIdx.x * blockDim.x + threadIdx.x;
    if (i <= n) g_cnt[i] = 0;
}

__global__ void hist_kernel(const void* ei, int E) {
    int e = blockIdx.x * blockDim.x + threadIdx.x;
    if (e >= E) return;
    int d = load_idx(ei, (long long)E + e);  // dst row
    atomicAdd(&g_cnt[d], 1);
}

// single-block scan: exclusive prefix over g_cnt[0..n) -> g_rp, g_fill; also g_inv
__global__ void scan_kernel(int n) {
    __shared__ int warp_sums[32];
    __shared__ int s_carry;
    int t = threadIdx.x;          // blockDim = 1024
    int lane = t & 31, wid = t >> 5;
    if (t == 0) s_carry = 0;
    __syncthreads();
    for (int base = 0; base < n; base += 1024) {
        int i = base + t;
        int v = (i < n) ? g_cnt[i] : 0;
        int x = v;
        #pragma unroll
        for (int off = 1; off < 32; off <<= 1) {
            int y = __shfl_up_sync(0xffffffffu, x, off);
            if (lane >= off) x += y;
        }
        if (lane == 31) warp_sums[wid] = x;
        __syncthreads();
        if (t < 32) {
            int w = warp_sums[t];
            #pragma unroll
            for (int off = 1; off < 32; off <<= 1) {
                int y = __shfl_up_sync(0xffffffffu, w, off);
                if (t >= off) w += y;
            }
            warp_sums[t] = w;
        }
        __syncthreads();
        int wadd = wid ? warp_sums[wid - 1] : 0;
        int incl = x + wadd;
        int carry = s_carry;
        int excl = incl - v + carry;
        if (i < n) {
            g_rp[i]   = excl;
            g_fill[i] = excl;
            g_inv[i]  = 1.0f / ((v > 0) ? (float)v : 1.0f);
        }
        __syncthreads();
        if (t == 1023) s_carry = carry + incl;
        __syncthreads();
    }
    if (t == 0) g_rp[n] = s_carry;
}

__global__ void fill_kernel(const void* ei, int E) {
    int e = blockIdx.x * blockDim.x + threadIdx.x;
    if (e >= E) return;
    int s = load_idx(ei, e);                  // src row
    int d = load_idx(ei, (long long)E + e);   // dst row
    int idx = atomicAdd(&g_fill[d], 1);
    g_col[idx] = s;
}

// ---------------- mean aggregation: one warp per node ----------------
__global__ void agg_kernel(const float* __restrict__ hin,
                           float* __restrict__ aggp, int n) {
    int w = (blockIdx.x * blockDim.x + threadIdx.x) >> 5;
    int lane = threadIdx.x & 31;
    if (w >= n) return;
    int start = g_rp[w], end = g_rp[w + 1];
    float4 acc = make_float4(0.f, 0.f, 0.f, 0.f);
    for (int e = start; e < end; e += 32) {
        int myc = (e + lane < end) ? g_col[e + lane] : 0;
        int m = min(32, end - e);
        for (int j = 0; j < m; ++j) {
            int s = __shfl_sync(0xffffffffu, myc, j);
            float4 v = *(const float4*)(hin + (size_t)s * D + 4 * lane);
            acc.x += v.x; acc.y += v.y; acc.z += v.z; acc.w += v.w;
        }
    }
    float inv = g_inv[w];
    float4 r = make_float4(acc.x * inv, acc.y * inv, acc.z * inv, acc.w * inv);
    *(float4*)(aggp + (size_t)w * D + 4 * lane) = r;
}

// ---------------- fused SGEMM: out = [relu](agg@Wl^T + h@Wr^T + b) ----------------
// BM=64, BN=128, K=256 (concat), BK=16, 256 threads, 4x8 microtile.
__global__ __launch_bounds__(256)
void gemm_kernel(const float* __restrict__ A0,   // agg  (K 0..127)
                 const float* __restrict__ A1,   // h    (K 128..255)
                 const float* __restrict__ Wl,
                 const float* __restrict__ Wr,
                 const float* __restrict__ bias,
                 float* __restrict__ out,
                 int n, int relu) {
    __shared__ float As[16][64];
    __shared__ float Bs[16][128];
    int tid = threadIdx.x;
    int m0 = blockIdx.x * 64;
    int tx = tid & 15;        // 8 output cols each: tx*8
    int ty = tid >> 4;        // 4 rows each: ty*4
    int anode = tid >> 2;     // 0..63 (A loads)
    int kq = (tid & 3) * 4;   // 0,4,8,12

    float acc[4][8];
    #pragma unroll
    for (int r = 0; r < 4; ++r)
        #pragma unroll
        for (int c = 0; c < 8; ++c) acc[r][c] = 0.f;

    for (int kc = 0; kc < 16; ++kc) {
        const float* Asrc = (kc < 8) ? A0 : A1;
        const float* Wsrc = (kc < 8) ? Wl : Wr;
        int klocal = (kc & 7) * 16;

        // A tile: [16 k][64 node], transposed on store
        float4 av = make_float4(0.f, 0.f, 0.f, 0.f);
        int grow = m0 + anode;
        if (grow < n) av = *(const float4*)(Asrc + (size_t)grow * D + klocal + kq);
        As[kq + 0][anode] = av.x; As[kq + 1][anode] = av.y;
        As[kq + 2][anode] = av.z; As[kq + 3][anode] = av.w;

        // B tile: Bs[k][o] = Wsrc[o][klocal+k]
        #pragma unroll
        for (int p = 0; p < 2; ++p) {
            int o = (tid >> 2) + 64 * p;
            float4 wv = *(const float4*)(Wsrc + (size_t)o * D + klocal + kq);
            Bs[kq + 0][o] = wv.x; Bs[kq + 1][o] = wv.y;
            Bs[kq + 2][o] = wv.z; Bs[kq + 3][o] = wv.w;
        }
        __syncthreads();

        #pragma unroll
        for (int k = 0; k < 16; ++k) {
            float4 a  = *(const float4*)&As[k][ty * 4];
            float4 b0 = *(const float4*)&Bs[k][tx * 8];
            float4 b1 = *(const float4*)&Bs[k][tx * 8 + 4];
            float avv[4] = {a.x, a.y, a.z, a.w};
            float bvv[8] = {b0.x, b0.y, b0.z, b0.w, b1.x, b1.y, b1.z, b1.w};
            #pragma unroll
            for (int r = 0; r < 4; ++r)
                #pragma unroll
                for (int c = 0; c < 8; ++c)
                    acc[r][c] += avv[r] * bvv[c];
        }
        __syncthreads();
    }

    #pragma unroll
    for (int r = 0; r < 4; ++r) {
        int row = m0 + ty * 4 + r;
        if (row < n) {
            #pragma unroll
            for (int c = 0; c < 8; ++c) {
                float v = acc[r][c] + bias[tx * 8 + c];
                if (relu) v = fmaxf(v, 0.0f);
                acc[r][c] = v;
            }
            float4* op = (float4*)(out + (size_t)row * D + tx * 8);
            op[0] = make_float4(acc[r][0], acc[r][1], acc[r][2], acc[r][3]);
            op[1] = make_float4(acc[r][4], acc[r][5], acc[r][6], acc[r][7]);
        }
    }
}

// ---------------- launch ----------------
extern "C" void kernel_launch(void* const* d_in, const int* in_sizes, int n_in,
                              void* d_out, int out_size) {
    const float* x   = (const float*)d_in[0];
    const void*  ei  = d_in[1];
    const float* W1l = (const float*)d_in[2];
    const float* b1  = (const float*)d_in[3];
    const float* W1r = (const float*)d_in[4];
    const float* W2l = (const float*)d_in[5];
    const float* b2  = (const float*)d_in[6];
    const float* W2r = (const float*)d_in[7];
    const float* W3l = (const float*)d_in[8];
    const float* b3  = (const float*)d_in[9];
    const float* W3r = (const float*)d_in[10];
    float* out = (float*)d_out;

    int n = in_sizes[0] / D;     // 50000
    int E = in_sizes[1] / 2;     // 800000

    float *h1p, *h2p, *aggp;
    cudaGetSymbolAddress((void**)&h1p,  g_h1);
    cudaGetSymbolAddress((void**)&h2p,  g_h2);
    cudaGetSymbolAddress((void**)&aggp, g_agg);

    // --- CSR build (per call; kernel_launch must be stateless) ---
    detect_kernel<<<1, 256>>>(ei, E);
    zero_cnt_kernel<<<(n + 256) / 256, 256>>>(n);
    hist_kernel<<<(E + 255) / 256, 256>>>(ei, E);
    scan_kernel<<<1, 1024>>>(n);
    fill_kernel<<<(E + 255) / 256, 256>>>(ei, E);

    int agg_blocks  = (n * 32 + 255) / 256;
    int gemm_blocks = (n + 63) / 64;

    // layer 1: x -> h1 (relu)
    agg_kernel<<<agg_blocks, 256>>>(x, aggp, n);
    gemm_kernel<<<gemm_blocks, 256>>>(aggp, x, W1l, W1r, b1, h1p, n, 1);

    // layer 2: h1 -> h2 (relu)
    agg_kernel<<<agg_blocks, 256>>>(h1p, aggp, n);
    gemm_kernel<<<gemm_blocks, 256>>>(aggp, h1p, W2l, W2r, b2, h2p, n, 1);

    // layer 3: h2 -> out (no relu)
    agg_kernel<<<agg_blocks, 256>>>(h2p, aggp, n);
    gemm_kernel<<<gemm_blocks, 256>>>(aggp, h2p, W3l, W3r, b3, out, n, 0);
}

// round 4
// speedup vs baseline: 1.8718x; 1.8718x over previous
#include <cuda_runtime.h>
#include <cuda_bf16.h>
#include <mma.h>
#include <stdint.h>

using namespace nvcuda;

// ---------------- problem constants ----------------
#define NMAX 50000
#define EMAX 800000
#define D    128
#define TSTRIDE 40   // smem tile stride (elems): 80B rows -> conflict-free LDSM

// ---------------- device scratch ----------------
__device__ int   g_cnt[NMAX];
__device__ int   g_rp[NMAX];         // segment start per dst node
__device__ int   g_fill[NMAX];       // fill cursors
__device__ float g_inv[NMAX];        // 1/max(deg,1)
__device__ int   g_col[EMAX];        // src indices grouped by dst
__device__ int   g_tot;
__device__ int   g_is64;
__device__ float g_h1[NMAX * D];
__device__ float g_h2[NMAX * D];
__device__ __nv_bfloat16 g_Ahi[NMAX * D];
__device__ __nv_bfloat16 g_Alo[NMAX * D];
__device__ __nv_bfloat16 g_Hhi[NMAX * D];
__device__ __nv_bfloat16 g_Hlo[NMAX * D];
__device__ __nv_bfloat16 g_Whi[6 * D * D];
__device__ __nv_bfloat16 g_Wlo[6 * D * D];

// ---------------- edge-index dtype detection ----------------
__global__ void detect_kernel(const void* ei, int E) {
    const int* p = (const int*)ei;
    int t = threadIdx.x;
    int m = min(E, 2048);
    int bad = 0;
    for (int i = t; i < m; i += blockDim.x) bad |= p[2 * i + 1];
    __shared__ int s;
    if (t == 0) s = 0;
    __syncthreads();
    atomicOr(&s, bad);
    __syncthreads();
    if (t == 0) g_is64 = (s == 0) ? 1 : 0;
}

__device__ __forceinline__ int load_idx(const void* ei, long long pos) {
    if (g_is64) return (int)((const long long*)ei)[pos];
    return ((const int*)ei)[pos];
}

// ---------------- CSR build (no global scan) ----------------
__global__ void zero_kernel(int n) {
    int i = blockIdx.x * blockDim.x + threadIdx.x;
    if (i < n) g_cnt[i] = 0;
    if (i == 0) g_tot = 0;
}

__global__ void hist_kernel(const void* ei, int E) {
    int e = blockIdx.x * blockDim.x + threadIdx.x;
    if (e >= E) return;
    int d = load_idx(ei, (long long)E + e);
    atomicAdd(&g_cnt[d], 1);
}

// atomic segment assignment: warp-scan + one global atomicAdd per warp
__global__ void assign_kernel(int n) {
    int i = blockIdx.x * blockDim.x + threadIdx.x;
    int lane = threadIdx.x & 31;
    int c = (i < n) ? g_cnt[i] : 0;
    int x = c;
    #pragma unroll
    for (int off = 1; off < 32; off <<= 1) {
        int y = __shfl_up_sync(0xffffffffu, x, off);
        if (lane >= off) x += y;
    }
    int wsum = __shfl_sync(0xffffffffu, x, 31);
    int base = 0;
    if (lane == 31) base = atomicAdd(&g_tot, wsum);
    base = __shfl_sync(0xffffffffu, base, 31);
    int excl = base + x - c;
    if (i < n) {
        g_rp[i]   = excl;
        g_fill[i] = excl;
        g_inv[i]  = 1.0f / ((c > 0) ? (float)c : 1.0f);
    }
}

__global__ void fill_kernel(const void* ei, int E) {
    int e = blockIdx.x * blockDim.x + threadIdx.x;
    if (e >= E) return;
    int s = load_idx(ei, e);
    int d = load_idx(ei, (long long)E + e);
    int idx = atomicAdd(&g_fill[d], 1);
    g_col[idx] = s;
}

// ---------------- split-precision helpers ----------------
__device__ __forceinline__ void split2(float v, __nv_bfloat16& h, __nv_bfloat16& l) {
    h = __float2bfloat16(v);
    l = __float2bfloat16(v - __bfloat162float(h));
}

// ---------------- mean aggregation: one warp per node -> bf16 hi/lo ----------------
__global__ void agg_kernel(const float* __restrict__ hin,
                           __nv_bfloat16* __restrict__ ahi,
                           __nv_bfloat16* __restrict__ alo, int n) {
    int w = (blockIdx.x * blockDim.x + threadIdx.x) >> 5;
    int lane = threadIdx.x & 31;
    if (w >= n) return;
    int start = g_rp[w];
    int end = start + g_cnt[w];
    float4 acc = make_float4(0.f, 0.f, 0.f, 0.f);
    for (int e = start; e < end; e += 32) {
        int myc = (e + lane < end) ? g_col[e + lane] : 0;
        int m = min(32, end - e);
        for (int j = 0; j < m; ++j) {
            int s = __shfl_sync(0xffffffffu, myc, j);
            float4 v = *(const float4*)(hin + (size_t)s * D + 4 * lane);
            acc.x += v.x; acc.y += v.y; acc.z += v.z; acc.w += v.w;
        }
    }
    float inv = g_inv[w];
    float vs[4] = {acc.x * inv, acc.y * inv, acc.z * inv, acc.w * inv};
    __nv_bfloat16 h[4], l[4];
    #pragma unroll
    for (int q = 0; q < 4; ++q) split2(vs[q], h[q], l[q]);
    __nv_bfloat162 ph0, ph1, pl0, pl1;
    ph0.x = h[0]; ph0.y = h[1]; ph1.x = h[2]; ph1.y = h[3];
    pl0.x = l[0]; pl0.y = l[1]; pl1.x = l[2]; pl1.y = l[3];
    size_t off = (size_t)w * D + 4 * lane;
    *(uint2*)(ahi + off) = make_uint2(*(unsigned*)&ph0, *(unsigned*)&ph1);
    *(uint2*)(alo + off) = make_uint2(*(unsigned*)&pl0, *(unsigned*)&pl1);
}

// ---------------- conversions ----------------
__global__ void xconv_kernel(const float* __restrict__ x,
                             __nv_bfloat16* __restrict__ hhi,
                             __nv_bfloat16* __restrict__ hlo, int total4) {
    int i = blockIdx.x * blockDim.x + threadIdx.x;
    if (i >= total4) return;
    float4 v = *(const float4*)(x + 4 * i);
    float vs[4] = {v.x, v.y, v.z, v.w};
    __nv_bfloat16 h[4], l[4];
    #pragma unroll
    for (int q = 0; q < 4; ++q) split2(vs[q], h[q], l[q]);
    __nv_bfloat162 ph0, ph1, pl0, pl1;
    ph0.x = h[0]; ph0.y = h[1]; ph1.x = h[2]; ph1.y = h[3];
    pl0.x = l[0]; pl0.y = l[1]; pl1.x = l[2]; pl1.y = l[3];
    *(uint2*)(hhi + 4 * i) = make_uint2(*(unsigned*)&ph0, *(unsigned*)&ph1);
    *(uint2*)(hlo + 4 * i) = make_uint2(*(unsigned*)&pl0, *(unsigned*)&pl1);
}

__global__ void wconv_kernel(const float* __restrict__ w0, const float* __restrict__ w1,
                             const float* __restrict__ w2, const float* __restrict__ w3,
                             const float* __restrict__ w4, const float* __restrict__ w5) {
    int i = blockIdx.x * blockDim.x + threadIdx.x;  // 6*16384 total
    if (i >= 6 * D * D) return;
    int m = i >> 14, off = i & (D * D - 1);
    const float* src;
    switch (m) {
        case 0: src = w0; break; case 1: src = w1; break;
        case 2: src = w2; break; case 3: src = w3; break;
        case 4: src = w4; break; default: src = w5; break;
    }
    float v = src[off];
    __nv_bfloat16 h, l;
    split2(v, h, l);
    g_Whi[i] = h;
    g_Wlo[i] = l;
}

// ---------------- tensor-core GEMM ----------------
// out[m][o] = [relu]( sum_k A[m][k]*Wl[o][k] + H[m][k]*Wr[o][k] + b[o] )
// bf16 split: C += Ahi*Whi + Ahi*Wlo + Alo*Whi  (per source)
// Block: 128x128, 8 warps, warp tile 32x64 (2x4 frags of 16x16).
#define BK 32

__global__ __launch_bounds__(256)
void gemm_kernel(const __nv_bfloat16* __restrict__ Ahi, const __nv_bfloat16* __restrict__ Alo,
                 const __nv_bfloat16* __restrict__ Hhi, const __nv_bfloat16* __restrict__ Hlo,
                 const __nv_bfloat16* __restrict__ Wlhi, const __nv_bfloat16* __restrict__ Wllo,
                 const __nv_bfloat16* __restrict__ Wrhi, const __nv_bfloat16* __restrict__ Wrlo,
                 const float* __restrict__ bias,
                 float* __restrict__ out,
                 __nv_bfloat16* __restrict__ Ohi, __nv_bfloat16* __restrict__ Olo,
                 int n, int relu, int writeHL) {
    extern __shared__ char smraw[];
    __nv_bfloat16* As_hi = (__nv_bfloat16*)smraw;
    __nv_bfloat16* As_lo = As_hi + 128 * TSTRIDE;
    __nv_bfloat16* Ws_hi = As_lo + 128 * TSTRIDE;
    __nv_bfloat16* Ws_lo = Ws_hi + 128 * TSTRIDE;
    float* Csm = (float*)smraw;

    int tid = threadIdx.x;
    int wid = tid >> 5;
    int warp_m = wid & 3;
    int warp_n = wid >> 2;
    int m0 = blockIdx.x * 128;

    wmma::fragment<wmma::accumulator, 16, 16, 16, float> acc[2][4];
    #pragma unroll
    for (int i = 0; i < 2; ++i)
        #pragma unroll
        for (int j = 0; j < 4; ++j) wmma::fill_fragment(acc[i][j], 0.0f);

    int lrow = tid >> 1;          // 0..127
    int lcol = (tid & 1) * 16;    // 0 or 16
    int grow = m0 + lrow;
    bool rowok = grow < n;
    uint4 z4 = make_uint4(0, 0, 0, 0);

    #pragma unroll
    for (int s = 0; s < 2; ++s) {
        const __nv_bfloat16* Asrc_hi = s ? Hhi : Ahi;
        const __nv_bfloat16* Asrc_lo = s ? Hlo : Alo;
        const __nv_bfloat16* Wsrc_hi = s ? Wrhi : Wlhi;
        const __nv_bfloat16* Wsrc_lo = s ? Wrlo : Wllo;
        for (int k0 = 0; k0 < D; k0 += BK) {
            __syncthreads();
            // A tiles
            {
                size_t go = (size_t)grow * D + k0 + lcol;
                uint4 v0 = rowok ? ((const uint4*)(Asrc_hi + go))[0] : z4;
                uint4 v1 = rowok ? ((const uint4*)(Asrc_hi + go))[1] : z4;
                *(uint4*)(As_hi + lrow * TSTRIDE + lcol) = v0;
                *(uint4*)(As_hi + lrow * TSTRIDE + lcol + 8) = v1;
                uint4 w0 = rowok ? ((const uint4*)(Asrc_lo + go))[0] : z4;
                uint4 w1 = rowok ? ((const uint4*)(Asrc_lo + go))[1] : z4;
                *(uint4*)(As_lo + lrow * TSTRIDE + lcol) = w0;
                *(uint4*)(As_lo + lrow * TSTRIDE + lcol + 8) = w1;
            }
            // W tiles (o rows 0..127)
            {
                size_t wo = (size_t)lrow * D + k0 + lcol;
                uint4 q0 = ((const uint4*)(Wsrc_hi + wo))[0];
                uint4 q1 = ((const uint4*)(Wsrc_hi + wo))[1];
                *(uint4*)(Ws_hi + lrow * TSTRIDE + lcol) = q0;
                *(uint4*)(Ws_hi + lrow * TSTRIDE + lcol + 8) = q1;
                uint4 r0 = ((const uint4*)(Wsrc_lo + wo))[0];
                uint4 r1 = ((const uint4*)(Wsrc_lo + wo))[1];
                *(uint4*)(Ws_lo + lrow * TSTRIDE + lcol) = r0;
                *(uint4*)(Ws_lo + lrow * TSTRIDE + lcol + 8) = r1;
            }
            __syncthreads();
            #pragma unroll
            for (int kk = 0; kk < BK; kk += 16) {
                wmma::fragment<wmma::matrix_a, 16, 16, 16, __nv_bfloat16, wmma::row_major> a_hi[2], a_lo[2];
                #pragma unroll
                for (int i = 0; i < 2; ++i) {
                    int mrow = warp_m * 32 + i * 16;
                    wmma::load_matrix_sync(a_hi[i], As_hi + mrow * TSTRIDE + kk, TSTRIDE);
                    wmma::load_matrix_sync(a_lo[i], As_lo + mrow * TSTRIDE + kk, TSTRIDE);
                }
                #pragma unroll
                for (int j = 0; j < 4; ++j) {
                    wmma::fragment<wmma::matrix_b, 16, 16, 16, __nv_bfloat16, wmma::col_major> b_hi, b_lo;
                    int orow = warp_n * 64 + j * 16;
                    wmma::load_matrix_sync(b_hi, Ws_hi + orow * TSTRIDE + kk, TSTRIDE);
                    wmma::load_matrix_sync(b_lo, Ws_lo + orow * TSTRIDE + kk, TSTRIDE);
                    #pragma unroll
                    for (int i = 0; i < 2; ++i) {
                        wmma::mma_sync(acc[i][j], a_hi[i], b_hi, acc[i][j]);
                        wmma::mma_sync(acc[i][j], a_hi[i], b_lo, acc[i][j]);
                        wmma::mma_sync(acc[i][j], a_lo[i], b_hi, acc[i][j]);
                    }
                }
            }
        }
    }
    __syncthreads();
    #pragma unroll
    for (int i = 0; i < 2; ++i)
        #pragma unroll
        for (int j = 0; j < 4; ++j)
            wmma::store_matrix_sync(Csm + (warp_m * 32 + i * 16) * 128 + warp_n * 64 + j * 16,
                                    acc[i][j], 128, wmma::mem_row_major);
    __syncthreads();

    // epilogue: bias + relu, write fp32 out (+ bf16 hi/lo self-term for next layer)
    #pragma unroll
    for (int it = 0; it < 16; ++it) {
        int e = (it * 256 + tid) * 4;          // element index in 128x128 tile
        int row = e >> 7;
        int col = e & 127;
        int gr = m0 + row;
        if (gr >= n) continue;
        float4 v = *(float4*)(Csm + e);
        float4 b = *(const float4*)(bias + col);
        v.x += b.x; v.y += b.y; v.z += b.z; v.w += b.w;
        if (relu) {
            v.x = fmaxf(v.x, 0.f); v.y = fmaxf(v.y, 0.f);
            v.z = fmaxf(v.z, 0.f); v.w = fmaxf(v.w, 0.f);
        }
        size_t go = (size_t)gr * D + col;
        *(float4*)(out + go) = v;
        if (writeHL) {
            float vs[4] = {v.x, v.y, v.z, v.w};
            __nv_bfloat16 h[4], l[4];
            #pragma unroll
            for (int q = 0; q < 4; ++q) split2(vs[q], h[q], l[q]);
            __nv_bfloat162 ph0, ph1, pl0, pl1;
            ph0.x = h[0]; ph0.y = h[1]; ph1.x = h[2]; ph1.y = h[3];
            pl0.x = l[0]; pl0.y = l[1]; pl1.x = l[2]; pl1.y = l[3];
            *(uint2*)(Ohi + go) = make_uint2(*(unsigned*)&ph0, *(unsigned*)&ph1);
            *(uint2*)(Olo + go) = make_uint2(*(unsigned*)&pl0, *(unsigned*)&pl1);
        }
    }
}

// ---------------- launch ----------------
extern "C" void kernel_launch(void* const* d_in, const int* in_sizes, int n_in,
                              void* d_out, int out_size) {
    const float* x   = (const float*)d_in[0];
    const void*  ei  = d_in[1];
    const float* W1l = (const float*)d_in[2];
    const float* b1  = (const float*)d_in[3];
    const float* W1r = (const float*)d_in[4];
    const float* W2l = (const float*)d_in[5];
    const float* b2  = (const float*)d_in[6];
    const float* W2r = (const float*)d_in[7];
    const float* W3l = (const float*)d_in[8];
    const float* b3  = (const float*)d_in[9];
    const float* W3r = (const float*)d_in[10];
    float* out = (float*)d_out;

    int n = in_sizes[0] / D;
    int E = in_sizes[1] / 2;

    float *h1p, *h2p;
    __nv_bfloat16 *ahip, *alop, *hhip, *hlop, *whip, *wlop;
    cudaGetSymbolAddress((void**)&h1p,  g_h1);
    cudaGetSymbolAddress((void**)&h2p,  g_h2);
    cudaGetSymbolAddress((void**)&ahip, g_Ahi);
    cudaGetSymbolAddress((void**)&alop, g_Alo);
    cudaGetSymbolAddress((void**)&hhip, g_Hhi);
    cudaGetSymbolAddress((void**)&hlop, g_Hlo);
    cudaGetSymbolAddress((void**)&whip, g_Whi);
    cudaGetSymbolAddress((void**)&wlop, g_Wlo);

    static bool attr_done = false;
    if (!attr_done) {
        cudaFuncSetAttribute(gemm_kernel, cudaFuncAttributeMaxDynamicSharedMemorySize, 65536);
        attr_done = true;
    }

    // CSR build
    detect_kernel<<<1, 256>>>(ei, E);
    zero_kernel<<<(n + 255) / 256, 256>>>(n);
    hist_kernel<<<(E + 255) / 256, 256>>>(ei, E);
    assign_kernel<<<(n + 255) / 256, 256>>>(n);
    fill_kernel<<<(E + 255) / 256, 256>>>(ei, E);

    // weight + input conversion
    wconv_kernel<<<(6 * D * D + 255) / 256, 256>>>(W1l, W1r, W2l, W2r, W3l, W3r);
    int total4 = n * D / 4;
    xconv_kernel<<<(total4 + 255) / 256, 256>>>(x, hhip, hlop, total4);

    int agg_blocks  = (n * 32 + 255) / 256;
    int gemm_blocks = (n + 127) / 128;
    const int SMEM = 65536;

    // layer 1
    agg_kernel<<<agg_blocks, 256>>>(x, ahip, alop, n);
    gemm_kernel<<<gemm_blocks, 256, SMEM>>>(ahip, alop, hhip, hlop,
        whip + 0 * D * D, wlop + 0 * D * D, whip + 1 * D * D, wlop + 1 * D * D,
        b1, h1p, hhip, hlop, n, 1, 1);
    // layer 2
    agg_kernel<<<agg_blocks, 256>>>(h1p, ahip, alop, n);
    gemm_kernel<<<gemm_blocks, 256, SMEM>>>(ahip, alop, hhip, hlop,
        whip + 2 * D * D, wlop + 2 * D * D, whip + 3 * D * D, wlop + 3 * D * D,
        b2, h2p, hhip, hlop, n, 1, 1);
    // layer 3
    agg_kernel<<<agg_blocks, 256>>>(h2p, ahip, alop, n);
    gemm_kernel<<<gemm_blocks, 256, SMEM>>>(ahip, alop, hhip, hlop,
        whip + 4 * D * D, wlop + 4 * D * D, whip + 5 * D * D, wlop + 5 * D * D,
        b3, out, hhip, hlop, n, 0, 0);
}

// round 5
// speedup vs baseline: 2.3294x; 1.2445x over previous
#include <cuda_runtime.h>
#include <cuda_fp16.h>
#include <cuda_bf16.h>
#include <mma.h>
#include <stdint.h>

using namespace nvcuda;

// ---------------- problem constants ----------------
#define NMAX 50000
#define EMAX 800000
#define D    128
#define TSTRIDE 40        // smem tile stride (elems): 80B rows
#define BK 32
#define TILE_BYTES (128 * TSTRIDE * 2)      // 10240 B per bf16 tile
#define BUF_BYTES  (4 * TILE_BYTES)         // 40960 B per stage (4 tiles)
#define SMEM_TOTAL (2 * BUF_BYTES)          // 81920 B

// ---------------- device scratch ----------------
__device__ int   g_cnt[NMAX];
__device__ int   g_rp[NMAX];
__device__ int   g_fill[NMAX];
__device__ float g_inv[NMAX];
__device__ int   g_col[EMAX];
__device__ int   g_tot;
__device__ int   g_is64;
__device__ __align__(16) __half         g_act[NMAX * D];      // fp16 gather buffer
__device__ __align__(16) __nv_bfloat16  g_Ahi[NMAX * D];
__device__ __align__(16) __nv_bfloat16  g_Alo[NMAX * D];
__device__ __align__(16) __nv_bfloat16  g_Hhi[NMAX * D];
__device__ __align__(16) __nv_bfloat16  g_Hlo[NMAX * D];
__device__ __align__(16) __nv_bfloat16  g_Whi[6 * D * D];
__device__ __align__(16) __nv_bfloat16  g_Wlo[6 * D * D];

// ---------------- helpers ----------------
__device__ __forceinline__ unsigned smem_u32(const void* p) {
    unsigned a;
    asm("{ .reg .u64 t; cvta.to.shared.u64 t, %1; cvt.u32.u64 %0, t; }"
        : "=r"(a) : "l"(p));
    return a;
}

__device__ __forceinline__ void cp16(unsigned sdst, const void* gsrc) {
    asm volatile("cp.async.cg.shared.global [%0], [%1], 16;"
                 :: "r"(sdst), "l"(gsrc));
}

__device__ __forceinline__ void split2(float v, __nv_bfloat16& h, __nv_bfloat16& l) {
    h = __float2bfloat16(v);
    l = __float2bfloat16(v - __bfloat162float(h));
}

// ---------------- edge-index dtype detection ----------------
__global__ void detect_kernel(const void* ei, int E) {
    const int* p = (const int*)ei;
    int t = threadIdx.x;
    int m = min(E, 2048);
    int bad = 0;
    for (int i = t; i < m; i += blockDim.x) bad |= p[2 * i + 1];
    __shared__ int s;
    if (t == 0) s = 0;
    __syncthreads();
    atomicOr(&s, bad);
    __syncthreads();
    if (t == 0) g_is64 = (s == 0) ? 1 : 0;
}

__device__ __forceinline__ int load_idx(const void* ei, long long pos) {
    if (g_is64) return (int)((const long long*)ei)[pos];
    return ((const int*)ei)[pos];
}

// ---------------- CSR build ----------------
__global__ void zero_kernel(int n) {
    int i = blockIdx.x * blockDim.x + threadIdx.x;
    if (i < n) g_cnt[i] = 0;
    if (i == 0) g_tot = 0;
}

__global__ void hist_kernel(const void* ei, int E) {
    int e = blockIdx.x * blockDim.x + threadIdx.x;
    if (e >= E) return;
    int d = load_idx(ei, (long long)E + e);
    atomicAdd(&g_cnt[d], 1);
}

__global__ void assign_kernel(int n) {
    int i = blockIdx.x * blockDim.x + threadIdx.x;
    int lane = threadIdx.x & 31;
    int c = (i < n) ? g_cnt[i] : 0;
    int x = c;
    #pragma unroll
    for (int off = 1; off < 32; off <<= 1) {
        int y = __shfl_up_sync(0xffffffffu, x, off);
        if (lane >= off) x += y;
    }
    int wsum = __shfl_sync(0xffffffffu, x, 31);
    int base = 0;
    if (lane == 31) base = atomicAdd(&g_tot, wsum);
    base = __shfl_sync(0xffffffffu, base, 31);
    int excl = base + x - c;
    if (i < n) {
        g_rp[i]   = excl;
        g_fill[i] = excl;
        g_inv[i]  = 1.0f / ((c > 0) ? (float)c : 1.0f);
    }
}

__global__ void fill_kernel(const void* ei, int E) {
    int e = blockIdx.x * blockDim.x + threadIdx.x;
    if (e >= E) return;
    int s = load_idx(ei, e);
    int d = load_idx(ei, (long long)E + e);
    int idx = atomicAdd(&g_fill[d], 1);
    g_col[idx] = s;
}

// ---------------- conversions ----------------
__global__ void xconv_kernel(const float* __restrict__ x,
                             __half* __restrict__ act,
                             __nv_bfloat16* __restrict__ hhi,
                             __nv_bfloat16* __restrict__ hlo, int total4) {
    int i = blockIdx.x * blockDim.x + threadIdx.x;
    if (i >= total4) return;
    float4 v = *(const float4*)(x + 4 * i);
    float vs[4] = {v.x, v.y, v.z, v.w};
    __nv_bfloat16 h[4], l[4];
    #pragma unroll
    for (int q = 0; q < 4; ++q) split2(vs[q], h[q], l[q]);
    __nv_bfloat162 ph0, ph1, pl0, pl1;
    ph0.x = h[0]; ph0.y = h[1]; ph1.x = h[2]; ph1.y = h[3];
    pl0.x = l[0]; pl0.y = l[1]; pl1.x = l[2]; pl1.y = l[3];
    *(uint2*)(hhi + 4 * i) = make_uint2(*(unsigned*)&ph0, *(unsigned*)&ph1);
    *(uint2*)(hlo + 4 * i) = make_uint2(*(unsigned*)&pl0, *(unsigned*)&pl1);
    __half2 a0 = __floats2half2_rn(v.x, v.y);
    __half2 a1 = __floats2half2_rn(v.z, v.w);
    *(uint2*)(act + 4 * i) = make_uint2(*(unsigned*)&a0, *(unsigned*)&a1);
}

__global__ void wconv_kernel(const float* __restrict__ w0, const float* __restrict__ w1,
                             const float* __restrict__ w2, const float* __restrict__ w3,
                             const float* __restrict__ w4, const float* __restrict__ w5) {
    int i = blockIdx.x * blockDim.x + threadIdx.x;
    if (i >= 6 * D * D) return;
    int m = i >> 14, off = i & (D * D - 1);
    const float* src;
    switch (m) {
        case 0: src = w0; break; case 1: src = w1; break;
        case 2: src = w2; break; case 3: src = w3; break;
        case 4: src = w4; break; default: src = w5; break;
    }
    float v = src[off];
    __nv_bfloat16 h, l;
    split2(v, h, l);
    g_Whi[i] = h;
    g_Wlo[i] = l;
}

// ---------------- mean aggregation (fp16 gather, fp32 accumulate) ----------------
__device__ __forceinline__ void acc_add(float4& acc, uint2 v) {
    __half2 h0 = *(__half2*)&v.x;
    __half2 h1 = *(__half2*)&v.y;
    float2 f0 = __half22float2(h0);
    float2 f1 = __half22float2(h1);
    acc.x += f0.x; acc.y += f0.y; acc.z += f1.x; acc.w += f1.y;
}

__global__ void agg_kernel(const __half* __restrict__ hin,
                           __nv_bfloat16* __restrict__ ahi,
                           __nv_bfloat16* __restrict__ alo, int n) {
    int w = (blockIdx.x * blockDim.x + threadIdx.x) >> 5;
    int lane = threadIdx.x & 31;
    if (w >= n) return;
    int start = g_rp[w];
    int end = start + g_cnt[w];
    float4 acc = make_float4(0.f, 0.f, 0.f, 0.f);
    for (int e = start; e < end; e += 32) {
        int myc = (e + lane < end) ? g_col[e + lane] : 0;
        int m = min(32, end - e);
        int j = 0;
        for (; j + 4 <= m; j += 4) {
            int s0 = __shfl_sync(0xffffffffu, myc, j + 0);
            int s1 = __shfl_sync(0xffffffffu, myc, j + 1);
            int s2 = __shfl_sync(0xffffffffu, myc, j + 2);
            int s3 = __shfl_sync(0xffffffffu, myc, j + 3);
            uint2 v0 = *(const uint2*)(hin + (size_t)s0 * D + 4 * lane);
            uint2 v1 = *(const uint2*)(hin + (size_t)s1 * D + 4 * lane);
            uint2 v2 = *(const uint2*)(hin + (size_t)s2 * D + 4 * lane);
            uint2 v3 = *(const uint2*)(hin + (size_t)s3 * D + 4 * lane);
            acc_add(acc, v0); acc_add(acc, v1);
            acc_add(acc, v2); acc_add(acc, v3);
        }
        for (; j < m; ++j) {
            int s = __shfl_sync(0xffffffffu, myc, j);
            uint2 v = *(const uint2*)(hin + (size_t)s * D + 4 * lane);
            acc_add(acc, v);
        }
    }
    float inv = g_inv[w];
    float vs[4] = {acc.x * inv, acc.y * inv, acc.z * inv, acc.w * inv};
    __nv_bfloat16 h[4], l[4];
    #pragma unroll
    for (int q = 0; q < 4; ++q) split2(vs[q], h[q], l[q]);
    __nv_bfloat162 ph0, ph1, pl0, pl1;
    ph0.x = h[0]; ph0.y = h[1]; ph1.x = h[2]; ph1.y = h[3];
    pl0.x = l[0]; pl0.y = l[1]; pl1.x = l[2]; pl1.y = l[3];
    size_t off = (size_t)w * D + 4 * lane;
    *(uint2*)(ahi + off) = make_uint2(*(unsigned*)&ph0, *(unsigned*)&ph1);
    *(uint2*)(alo + off) = make_uint2(*(unsigned*)&pl0, *(unsigned*)&pl1);
}

// ---------------- tensor-core GEMM, cp.async double-buffered ----------------
// out[m][o] = [relu]( sum_k A[m][k]*Wl[o][k] + H[m][k]*Wr[o][k] + b[o] )
// bf16 split: Ahi*Whi + Ahi*Wlo + Alo*Whi per source. 8 k-chunks (2 src x 4).
__global__ __launch_bounds__(256)
void gemm_kernel(const __nv_bfloat16* __restrict__ Ahi, const __nv_bfloat16* __restrict__ Alo,
                 const __nv_bfloat16* __restrict__ Hhi, const __nv_bfloat16* __restrict__ Hlo,
                 const __nv_bfloat16* __restrict__ Wlhi, const __nv_bfloat16* __restrict__ Wllo,
                 const __nv_bfloat16* __restrict__ Wrhi, const __nv_bfloat16* __restrict__ Wrlo,
                 const float* __restrict__ bias,
                 float* __restrict__ out, __half* __restrict__ actout,
                 __nv_bfloat16* __restrict__ Ohi, __nv_bfloat16* __restrict__ Olo,
                 int n, int relu, int fin) {
    extern __shared__ char smraw[];
    float* Csm = (float*)smraw;

    int tid = threadIdx.x;
    int wid = tid >> 5;
    int warp_m = wid & 3;
    int warp_n = wid >> 2;
    int m0 = blockIdx.x * 128;

    wmma::fragment<wmma::accumulator, 16, 16, 16, float> acc[2][4];
    #pragma unroll
    for (int i = 0; i < 2; ++i)
        #pragma unroll
        for (int j = 0; j < 4; ++j) wmma::fill_fragment(acc[i][j], 0.0f);

    int lrow = tid >> 1;          // 0..127
    int lcol = (tid & 1) * 16;    // 0 or 16
    int grow = m0 + lrow;
    int arow = (grow < n) ? grow : (n - 1);   // clamp; garbage rows discarded in epilogue
    unsigned soff = (unsigned)(lrow * TSTRIDE + lcol) * 2;  // byte offset within a tile

    unsigned sbase = smem_u32(smraw);

    // issue one chunk's cp.async copies into buffer b
    #define ISSUE(c, b) do {                                                   \
        int s_ = (c) >> 2, k0_ = ((c) & 3) * BK;                               \
        const __nv_bfloat16* ah_ = s_ ? Hhi : Ahi;                             \
        const __nv_bfloat16* al_ = s_ ? Hlo : Alo;                             \
        const __nv_bfloat16* wh_ = s_ ? Wrhi : Wlhi;                           \
        const __nv_bfloat16* wl_ = s_ ? Wrlo : Wllo;                           \
        unsigned bb_ = sbase + (b) * BUF_BYTES;                                \
        size_t ga_ = (size_t)arow * D + k0_ + lcol;                            \
        size_t gw_ = (size_t)lrow * D + k0_ + lcol;                            \
        cp16(bb_ + 0 * TILE_BYTES + soff,      ah_ + ga_);                     \
        cp16(bb_ + 0 * TILE_BYTES + soff + 16, ah_ + ga_ + 8);                 \
        cp16(bb_ + 1 * TILE_BYTES + soff,      al_ + ga_);                     \
        cp16(bb_ + 1 * TILE_BYTES + soff + 16, al_ + ga_ + 8);                 \
        cp16(bb_ + 2 * TILE_BYTES + soff,      wh_ + gw_);                     \
        cp16(bb_ + 2 * TILE_BYTES + soff + 16, wh_ + gw_ + 8);                 \
        cp16(bb_ + 3 * TILE_BYTES + soff,      wl_ + gw_);                     \
        cp16(bb_ + 3 * TILE_BYTES + soff + 16, wl_ + gw_ + 8);                 \
        asm volatile("cp.async.commit_group;");                                \
    } while (0)

    ISSUE(0, 0);

    for (int c = 0; c < 8; ++c) {
        asm volatile("cp.async.wait_group 0;");
        __syncthreads();
        if (c < 7) ISSUE(c + 1, (c + 1) & 1);

        char* bb = smraw + (c & 1) * BUF_BYTES;
        __nv_bfloat16* As_hi = (__nv_bfloat16*)(bb + 0 * TILE_BYTES);
        __nv_bfloat16* As_lo = (__nv_bfloat16*)(bb + 1 * TILE_BYTES);
        __nv_bfloat16* Ws_hi = (__nv_bfloat16*)(bb + 2 * TILE_BYTES);
        __nv_bfloat16* Ws_lo = (__nv_bfloat16*)(bb + 3 * TILE_BYTES);

        #pragma unroll
        for (int kk = 0; kk < BK; kk += 16) {
            wmma::fragment<wmma::matrix_a, 16, 16, 16, __nv_bfloat16, wmma::row_major> a_hi[2], a_lo[2];
            #pragma unroll
            for (int i = 0; i < 2; ++i) {
                int mrow = warp_m * 32 + i * 16;
                wmma::load_matrix_sync(a_hi[i], As_hi + mrow * TSTRIDE + kk, TSTRIDE);
                wmma::load_matrix_sync(a_lo[i], As_lo + mrow * TSTRIDE + kk, TSTRIDE);
            }
            #pragma unroll
            for (int j = 0; j < 4; ++j) {
                wmma::fragment<wmma::matrix_b, 16, 16, 16, __nv_bfloat16, wmma::col_major> b_hi, b_lo;
                int orow = warp_n * 64 + j * 16;
                wmma::load_matrix_sync(b_hi, Ws_hi + orow * TSTRIDE + kk, TSTRIDE);
                wmma::load_matrix_sync(b_lo, Ws_lo + orow * TSTRIDE + kk, TSTRIDE);
                #pragma unroll
                for (int i = 0; i < 2; ++i) {
                    wmma::mma_sync(acc[i][j], a_hi[i], b_hi, acc[i][j]);
                    wmma::mma_sync(acc[i][j], a_hi[i], b_lo, acc[i][j]);
                    wmma::mma_sync(acc[i][j], a_lo[i], b_hi, acc[i][j]);
                }
            }
        }
    }
    __syncthreads();
    #pragma unroll
    for (int i = 0; i < 2; ++i)
        #pragma unroll
        for (int j = 0; j < 4; ++j)
            wmma::store_matrix_sync(Csm + (warp_m * 32 + i * 16) * 128 + warp_n * 64 + j * 16,
                                    acc[i][j], 128, wmma::mem_row_major);
    __syncthreads();

    // epilogue
    #pragma unroll
    for (int it = 0; it < 16; ++it) {
        int e = (it * 256 + tid) * 4;
        int row = e >> 7;
        int col = e & 127;
        int gr = m0 + row;
        if (gr >= n) continue;
        float4 v = *(float4*)(Csm + e);
        float4 b = *(const float4*)(bias + col);
        v.x += b.x; v.y += b.y; v.z += b.z; v.w += b.w;
        if (relu) {
            v.x = fmaxf(v.x, 0.f); v.y = fmaxf(v.y, 0.f);
            v.z = fmaxf(v.z, 0.f); v.w = fmaxf(v.w, 0.f);
        }
        size_t go = (size_t)gr * D + col;
        if (fin) {
            *(float4*)(out + go) = v;
        } else {
            __half2 a0 = __floats2half2_rn(v.x, v.y);
            __half2 a1 = __floats2half2_rn(v.z, v.w);
            *(uint2*)(actout + go) = make_uint2(*(unsigned*)&a0, *(unsigned*)&a1);
            float vs[4] = {v.x, v.y, v.z, v.w};
            __nv_bfloat16 h[4], l[4];
            #pragma unroll
            for (int q = 0; q < 4; ++q) split2(vs[q], h[q], l[q]);
            __nv_bfloat162 ph0, ph1, pl0, pl1;
            ph0.x = h[0]; ph0.y = h[1]; ph1.x = h[2]; ph1.y = h[3];
            pl0.x = l[0]; pl0.y = l[1]; pl1.x = l[2]; pl1.y = l[3];
            *(uint2*)(Ohi + go) = make_uint2(*(unsigned*)&ph0, *(unsigned*)&ph1);
            *(uint2*)(Olo + go) = make_uint2(*(unsigned*)&pl0, *(unsigned*)&pl1);
        }
    }
}

// ---------------- launch ----------------
extern "C" void kernel_launch(void* const* d_in, const int* in_sizes, int n_in,
                              void* d_out, int out_size) {
    const float* x   = (const float*)d_in[0];
    const void*  ei  = d_in[1];
    const float* W1l = (const float*)d_in[2];
    const float* b1  = (const float*)d_in[3];
    const float* W1r = (const float*)d_in[4];
    const float* W2l = (const float*)d_in[5];
    const float* b2  = (const float*)d_in[6];
    const float* W2r = (const float*)d_in[7];
    const float* W3l = (const float*)d_in[8];
    const float* b3  = (const float*)d_in[9];
    const float* W3r = (const float*)d_in[10];
    float* out = (float*)d_out;

    int n = in_sizes[0] / D;
    int E = in_sizes[1] / 2;

    __half* actp;
    __nv_bfloat16 *ahip, *alop, *hhip, *hlop, *whip, *wlop;
    cudaGetSymbolAddress((void**)&actp, g_act);
    cudaGetSymbolAddress((void**)&ahip, g_Ahi);
    cudaGetSymbolAddress((void**)&alop, g_Alo);
    cudaGetSymbolAddress((void**)&hhip, g_Hhi);
    cudaGetSymbolAddress((void**)&hlop, g_Hlo);
    cudaGetSymbolAddress((void**)&whip, g_Whi);
    cudaGetSymbolAddress((void**)&wlop, g_Wlo);

    cudaFuncSetAttribute(gemm_kernel, cudaFuncAttributeMaxDynamicSharedMemorySize, SMEM_TOTAL);

    // CSR build
    detect_kernel<<<1, 256>>>(ei, E);
    zero_kernel<<<(n + 255) / 256, 256>>>(n);
    hist_kernel<<<(E + 255) / 256, 256>>>(ei, E);
    assign_kernel<<<(n + 255) / 256, 256>>>(n);
    fill_kernel<<<(E + 255) / 256, 256>>>(ei, E);

    // conversions
    wconv_kernel<<<(6 * D * D + 255) / 256, 256>>>(W1l, W1r, W2l, W2r, W3l, W3r);
    int total4 = n * D / 4;
    xconv_kernel<<<(total4 + 255) / 256, 256>>>(x, actp, hhip, hlop, total4);

    int agg_blocks  = (n * 32 + 255) / 256;
    int gemm_blocks = (n + 127) / 128;

    // layer 1
    agg_kernel<<<agg_blocks, 256>>>(actp, ahip, alop, n);
    gemm_kernel<<<gemm_blocks, 256, SMEM_TOTAL>>>(ahip, alop, hhip, hlop,
        whip + 0 * D * D, wlop + 0 * D * D, whip + 1 * D * D, wlop + 1 * D * D,
        b1, out, actp, hhip, hlop, n, 1, 0);
    // layer 2
    agg_kernel<<<agg_blocks, 256>>>(actp, ahip, alop, n);
    gemm_kernel<<<gemm_blocks, 256, SMEM_TOTAL>>>(ahip, alop, hhip, hlop,
        whip + 2 * D * D, wlop + 2 * D * D, whip + 3 * D * D, wlop + 3 * D * D,
        b2, out, actp, hhip, hlop, n, 1, 0);
    // layer 3 (final: fp32 out)
    agg_kernel<<<agg_blocks, 256>>>(actp, ahip, alop, n);
    gemm_kernel<<<gemm_blocks, 256, SMEM_TOTAL>>>(ahip, alop, hhip, hlop,
        whip + 4 * D * D, wlop + 4 * D * D, whip + 5 * D * D, wlop + 5 * D * D,
        b3, out, actp, hhip, hlop, n, 0, 1);
}

// round 6
// speedup vs baseline: 2.9889x; 1.2831x over previous
#include <cuda_runtime.h>
#include <cuda_fp16.h>
#include <cuda_bf16.h>
#include <mma.h>
#include <stdint.h>

using namespace nvcuda;

// ---------------- problem constants ----------------
#define NMAX 50000
#define EMAX 800000
#define D    128
#define TSTRIDE 40        // smem tile stride (halves): 80B rows
#define BK 32
#define TILE_BYTES (128 * TSTRIDE * 2)      // 10240 B per fp16 tile
#define BUF_BYTES  (3 * TILE_BYTES)         // 30720 B per stage (A, Whi, Wlo)
#define SMEM_TOTAL 65536                    // max(2*BUF_BYTES, 128*128*4)

// ---------------- device scratch ----------------
__device__ int   g_cnt[NMAX];
__device__ int   g_rp[NMAX];
__device__ int   g_fill[NMAX];
__device__ float g_inv[NMAX];
__device__ int   g_col[EMAX];
__device__ int   g_tot;
__device__ int   g_is64;
__device__ __align__(16) __half g_act[NMAX * D];   // fp16 activations (gather + GEMM H)
__device__ __align__(16) __half g_agg[NMAX * D];   // fp16 aggregated means (GEMM A)
__device__ __align__(16) __half g_Whi[6 * D * D];
__device__ __align__(16) __half g_Wlo[6 * D * D];

// ---------------- helpers ----------------
__device__ __forceinline__ unsigned smem_u32(const void* p) {
    unsigned a;
    asm("{ .reg .u64 t; cvta.to.shared.u64 t, %1; cvt.u32.u64 %0, t; }"
        : "=r"(a) : "l"(p));
    return a;
}

__device__ __forceinline__ void cp16(unsigned sdst, const void* gsrc) {
    asm volatile("cp.async.cg.shared.global [%0], [%1], 16;"
                 :: "r"(sdst), "l"(gsrc));
}

// ---------------- edge-index dtype detection ----------------
__global__ void detect_kernel(const void* ei, int E) {
    const int* p = (const int*)ei;
    int t = threadIdx.x;
    int m = min(E, 2048);
    int bad = 0;
    for (int i = t; i < m; i += blockDim.x) bad |= p[2 * i + 1];
    __shared__ int s;
    if (t == 0) s = 0;
    __syncthreads();
    atomicOr(&s, bad);
    __syncthreads();
    if (t == 0) g_is64 = (s == 0) ? 1 : 0;
}

__device__ __forceinline__ int load_idx(const void* ei, long long pos) {
    if (g_is64) return (int)((const long long*)ei)[pos];
    return ((const int*)ei)[pos];
}

// ---------------- CSR build ----------------
__global__ void zero_kernel(int n) {
    int i = blockIdx.x * blockDim.x + threadIdx.x;
    if (i < n) g_cnt[i] = 0;
    if (i == 0) g_tot = 0;
}

__global__ void hist_kernel(const void* ei, int E) {
    int e = blockIdx.x * blockDim.x + threadIdx.x;
    if (e >= E) return;
    int d = load_idx(ei, (long long)E + e);
    atomicAdd(&g_cnt[d], 1);
}

__global__ void assign_kernel(int n) {
    int i = blockIdx.x * blockDim.x + threadIdx.x;
    int lane = threadIdx.x & 31;
    int c = (i < n) ? g_cnt[i] : 0;
    int x = c;
    #pragma unroll
    for (int off = 1; off < 32; off <<= 1) {
        int y = __shfl_up_sync(0xffffffffu, x, off);
        if (lane >= off) x += y;
    }
    int wsum = __shfl_sync(0xffffffffu, x, 31);
    int base = 0;
    if (lane == 31) base = atomicAdd(&g_tot, wsum);
    base = __shfl_sync(0xffffffffu, base, 31);
    int excl = base + x - c;
    if (i < n) {
        g_rp[i]   = excl;
        g_fill[i] = excl;
        g_inv[i]  = 1.0f / ((c > 0) ? (float)c : 1.0f);
    }
}

__global__ void fill_kernel(const void* ei, int E) {
    int e = blockIdx.x * blockDim.x + threadIdx.x;
    if (e >= E) return;
    int s = load_idx(ei, e);
    int d = load_idx(ei, (long long)E + e);
    int idx = atomicAdd(&g_fill[d], 1);
    g_col[idx] = s;
}

// ---------------- conversions ----------------
__global__ void xconv_kernel(const float* __restrict__ x,
                             __half* __restrict__ act, int total4) {
    int i = blockIdx.x * blockDim.x + threadIdx.x;
    if (i >= total4) return;
    float4 v = *(const float4*)(x + 4 * i);
    __half2 a0 = __floats2half2_rn(v.x, v.y);
    __half2 a1 = __floats2half2_rn(v.z, v.w);
    *(uint2*)(act + 4 * i) = make_uint2(*(unsigned*)&a0, *(unsigned*)&a1);
}

__global__ void wconv_kernel(const float* __restrict__ w0, const float* __restrict__ w1,
                             const float* __restrict__ w2, const float* __restrict__ w3,
                             const float* __restrict__ w4, const float* __restrict__ w5) {
    int i = blockIdx.x * blockDim.x + threadIdx.x;
    if (i >= 6 * D * D) return;
    int m = i >> 14, off = i & (D * D - 1);
    const float* src;
    switch (m) {
        case 0: src = w0; break; case 1: src = w1; break;
        case 2: src = w2; break; case 3: src = w3; break;
        case 4: src = w4; break; default: src = w5; break;
    }
    float v = src[off];
    __half h = __float2half_rn(v);
    __half l = __float2half_rn(v - __half2float(h));
    g_Whi[i] = h;
    g_Wlo[i] = l;
}

// ---------------- mean aggregation (fp16 gather, fp32 accumulate) ----------------
__device__ __forceinline__ void acc_add(float4& acc, uint2 v) {
    __half2 h0 = *(__half2*)&v.x;
    __half2 h1 = *(__half2*)&v.y;
    float2 f0 = __half22float2(h0);
    float2 f1 = __half22float2(h1);
    acc.x += f0.x; acc.y += f0.y; acc.z += f1.x; acc.w += f1.y;
}

__global__ void agg_kernel(const __half* __restrict__ hin,
                           __half* __restrict__ aout, int n) {
    int w = (blockIdx.x * blockDim.x + threadIdx.x) >> 5;
    int lane = threadIdx.x & 31;
    if (w >= n) return;
    int start = g_rp[w];
    int end = start + g_cnt[w];
    float4 acc = make_float4(0.f, 0.f, 0.f, 0.f);
    for (int e = start; e < end; e += 32) {
        int myc = (e + lane < end) ? g_col[e + lane] : 0;
        int m = min(32, end - e);
        int j = 0;
        for (; j + 4 <= m; j += 4) {
            int s0 = __shfl_sync(0xffffffffu, myc, j + 0);
            int s1 = __shfl_sync(0xffffffffu, myc, j + 1);
            int s2 = __shfl_sync(0xffffffffu, myc, j + 2);
            int s3 = __shfl_sync(0xffffffffu, myc, j + 3);
            uint2 v0 = *(const uint2*)(hin + (size_t)s0 * D + 4 * lane);
            uint2 v1 = *(const uint2*)(hin + (size_t)s1 * D + 4 * lane);
            uint2 v2 = *(const uint2*)(hin + (size_t)s2 * D + 4 * lane);
            uint2 v3 = *(const uint2*)(hin + (size_t)s3 * D + 4 * lane);
            acc_add(acc, v0); acc_add(acc, v1);
            acc_add(acc, v2); acc_add(acc, v3);
        }
        for (; j < m; ++j) {
            int s = __shfl_sync(0xffffffffu, myc, j);
            uint2 v = *(const uint2*)(hin + (size_t)s * D + 4 * lane);
            acc_add(acc, v);
        }
    }
    float inv = g_inv[w];
    __half2 p0 = __floats2half2_rn(acc.x * inv, acc.y * inv);
    __half2 p1 = __floats2half2_rn(acc.z * inv, acc.w * inv);
    *(uint2*)(aout + (size_t)w * D + 4 * lane) = make_uint2(*(unsigned*)&p0, *(unsigned*)&p1);
}

// ---------------- tensor-core GEMM, cp.async double-buffered ----------------
// out[m][o] = [relu]( sum_k A[m][k]*Wl[o][k] + H[m][k]*Wr[o][k] + b[o] )
// fp16 A single, fp16 W split: C += A*Whi + A*Wlo. 8 chunks (2 src x 4 k).
__global__ __launch_bounds__(256)
void gemm_kernel(const __half* __restrict__ Agg, const __half* __restrict__ Act,
                 const __half* __restrict__ Wlhi, const __half* __restrict__ Wllo,
                 const __half* __restrict__ Wrhi, const __half* __restrict__ Wrlo,
                 const float* __restrict__ bias,
                 float* __restrict__ out, __half* __restrict__ actout,
                 int n, int relu, int fin) {
    extern __shared__ char smraw[];
    float* Csm = (float*)smraw;

    int tid = threadIdx.x;
    int wid = tid >> 5;
    int warp_m = wid & 3;
    int warp_n = wid >> 2;
    int m0 = blockIdx.x * 128;

    wmma::fragment<wmma::accumulator, 16, 16, 16, float> acc[2][4];
    #pragma unroll
    for (int i = 0; i < 2; ++i)
        #pragma unroll
        for (int j = 0; j < 4; ++j) wmma::fill_fragment(acc[i][j], 0.0f);

    int lrow = tid >> 1;          // 0..127
    int lcol = (tid & 1) * 16;    // 0 or 16
    int grow = m0 + lrow;
    int arow = (grow < n) ? grow : (n - 1);   // clamp; garbage rows dropped in epilogue
    unsigned soff = (unsigned)(lrow * TSTRIDE + lcol) * 2;
    unsigned sbase = smem_u32(smraw);

    #define ISSUE(c, b) do {                                                   \
        int s_ = (c) >> 2, k0_ = ((c) & 3) * BK;                               \
        const __half* a_  = s_ ? Act : Agg;                                    \
        const __half* wh_ = s_ ? Wrhi : Wlhi;                                  \
        const __half* wl_ = s_ ? Wrlo : Wllo;                                  \
        unsigned bb_ = sbase + (b) * BUF_BYTES;                                \
        size_t ga_ = (size_t)arow * D + k0_ + lcol;                            \
        size_t gw_ = (size_t)lrow * D + k0_ + lcol;                            \
        cp16(bb_ + 0 * TILE_BYTES + soff,      a_  + ga_);                     \
        cp16(bb_ + 0 * TILE_BYTES + soff + 16, a_  + ga_ + 8);                 \
        cp16(bb_ + 1 * TILE_BYTES + soff,      wh_ + gw_);                     \
        cp16(bb_ + 1 * TILE_BYTES + soff + 16, wh_ + gw_ + 8);                 \
        cp16(bb_ + 2 * TILE_BYTES + soff,      wl_ + gw_);                     \
        cp16(bb_ + 2 * TILE_BYTES + soff + 16, wl_ + gw_ + 8);                 \
        asm volatile("cp.async.commit_group;");                                \
    } while (0)

    ISSUE(0, 0);

    for (int c = 0; c < 8; ++c) {
        asm volatile("cp.async.wait_group 0;");
        __syncthreads();
        if (c < 7) ISSUE(c + 1, (c + 1) & 1);

        char* bb = smraw + (c & 1) * BUF_BYTES;
        __half* As   = (__half*)(bb + 0 * TILE_BYTES);
        __half* Ws_h = (__half*)(bb + 1 * TILE_BYTES);
        __half* Ws_l = (__half*)(bb + 2 * TILE_BYTES);

        #pragma unroll
        for (int kk = 0; kk < BK; kk += 16) {
            wmma::fragment<wmma::matrix_a, 16, 16, 16, __half, wmma::row_major> a[2];
            #pragma unroll
            for (int i = 0; i < 2; ++i)
                wmma::load_matrix_sync(a[i], As + (warp_m * 32 + i * 16) * TSTRIDE + kk, TSTRIDE);
            #pragma unroll
            for (int j = 0; j < 4; ++j) {
                wmma::fragment<wmma::matrix_b, 16, 16, 16, __half, wmma::col_major> b_hi, b_lo;
                int orow = warp_n * 64 + j * 16;
                wmma::load_matrix_sync(b_hi, Ws_h + orow * TSTRIDE + kk, TSTRIDE);
                wmma::load_matrix_sync(b_lo, Ws_l + orow * TSTRIDE + kk, TSTRIDE);
                #pragma unroll
                for (int i = 0; i < 2; ++i) {
                    wmma::mma_sync(acc[i][j], a[i], b_hi, acc[i][j]);
                    wmma::mma_sync(acc[i][j], a[i], b_lo, acc[i][j]);
                }
            }
        }
    }
    __syncthreads();
    #pragma unroll
    for (int i = 0; i < 2; ++i)
        #pragma unroll
        for (int j = 0; j < 4; ++j)
            wmma::store_matrix_sync(Csm + (warp_m * 32 + i * 16) * 128 + warp_n * 64 + j * 16,
                                    acc[i][j], 128, wmma::mem_row_major);
    __syncthreads();

    #pragma unroll
    for (int it = 0; it < 16; ++it) {
        int e = (it * 256 + tid) * 4;
        int row = e >> 7;
        int col = e & 127;
        int gr = m0 + row;
        if (gr >= n) continue;
        float4 v = *(float4*)(Csm + e);
        float4 b = *(const float4*)(bias + col);
        v.x += b.x; v.y += b.y; v.z += b.z; v.w += b.w;
        if (relu) {
            v.x = fmaxf(v.x, 0.f); v.y = fmaxf(v.y, 0.f);
            v.z = fmaxf(v.z, 0.f); v.w = fmaxf(v.w, 0.f);
        }
        size_t go = (size_t)gr * D + col;
        if (fin) {
            *(float4*)(out + go) = v;
        } else {
            __half2 a0 = __floats2half2_rn(v.x, v.y);
            __half2 a1 = __floats2half2_rn(v.z, v.w);
            *(uint2*)(actout + go) = make_uint2(*(unsigned*)&a0, *(unsigned*)&a1);
        }
    }
}

// ---------------- launch ----------------
extern "C" void kernel_launch(void* const* d_in, const int* in_sizes, int n_in,
                              void* d_out, int out_size) {
    const float* x   = (const float*)d_in[0];
    const void*  ei  = d_in[1];
    const float* W1l = (const float*)d_in[2];
    const float* b1  = (const float*)d_in[3];
    const float* W1r = (const float*)d_in[4];
    const float* W2l = (const float*)d_in[5];
    const float* b2  = (const float*)d_in[6];
    const float* W2r = (const float*)d_in[7];
    const float* W3l = (const float*)d_in[8];
    const float* b3  = (const float*)d_in[9];
    const float* W3r = (const float*)d_in[10];
    float* out = (float*)d_out;

    int n = in_sizes[0] / D;
    int E = in_sizes[1] / 2;

    __half *actp, *aggp, *whip, *wlop;
    cudaGetSymbolAddress((void**)&actp, g_act);
    cudaGetSymbolAddress((void**)&aggp, g_agg);
    cudaGetSymbolAddress((void**)&whip, g_Whi);
    cudaGetSymbolAddress((void**)&wlop, g_Wlo);

    cudaFuncSetAttribute(gemm_kernel, cudaFuncAttributeMaxDynamicSharedMemorySize, SMEM_TOTAL);

    // CSR build
    detect_kernel<<<1, 256>>>(ei, E);
    zero_kernel<<<(n + 255) / 256, 256>>>(n);
    hist_kernel<<<(E + 255) / 256, 256>>>(ei, E);
    assign_kernel<<<(n + 255) / 256, 256>>>(n);
    fill_kernel<<<(E + 255) / 256, 256>>>(ei, E);

    // conversions
    wconv_kernel<<<(6 * D * D + 255) / 256, 256>>>(W1l, W1r, W2l, W2r, W3l, W3r);
    int total4 = n * D / 4;
    xconv_kernel<<<(total4 + 255) / 256, 256>>>(x, actp, total4);

    int agg_blocks  = (n * 32 + 255) / 256;
    int gemm_blocks = (n + 127) / 128;

    // layer 1
    agg_kernel<<<agg_blocks, 256>>>(actp, aggp, n);
    gemm_kernel<<<gemm_blocks, 256, SMEM_TOTAL>>>(aggp, actp,
        whip + 0 * D * D, wlop + 0 * D * D, whip + 1 * D * D, wlop + 1 * D * D,
        b1, out, actp, n, 1, 0);
    // layer 2
    agg_kernel<<<agg_blocks, 256>>>(actp, aggp, n);
    gemm_kernel<<<gemm_blocks, 256, SMEM_TOTAL>>>(aggp, actp,
        whip + 2 * D * D, wlop + 2 * D * D, whip + 3 * D * D, wlop + 3 * D * D,
        b2, out, actp, n, 1, 0);
    // layer 3 (final: fp32 out)
    agg_kernel<<<agg_blocks, 256>>>(actp, aggp, n);
    gemm_kernel<<<gemm_blocks, 256, SMEM_TOTAL>>>(aggp, actp,
        whip + 4 * D * D, wlop + 4 * D * D, whip + 5 * D * D, wlop + 5 * D * D,
        b3, out, actp, n, 0, 1);
}